// round 2
// baseline (speedup 1.0000x reference)
#include <cuda_runtime.h>
#include <cstdint>
#include <cstddef>

// Problem dims
#define VOCAB 32000
#define EMB   512
#define HID   512
#define BATCH 64
#define S_LEN 512

// ---------------------------------------------------------------------------
// Scratch + flags (no allocation allowed -> __device__ globals)
// ---------------------------------------------------------------------------
__device__ int   g_tok64;                            // 1 if tokens are int64
__device__ float g_xproj[(size_t)BATCH * S_LEN * HID]; // 64 MB scratch

// ---------------------------------------------------------------------------
// Small helpers: packed f32x2 math (Blackwell)
// ---------------------------------------------------------------------------
__device__ __forceinline__ unsigned long long packdup(float v) {
    unsigned long long r;
    asm("mov.b64 %0, {%1, %1};" : "=l"(r) : "f"(v));
    return r;
}
__device__ __forceinline__ void ffma2(unsigned long long& acc,
                                      unsigned long long a,
                                      unsigned long long b) {
    asm("fma.rn.f32x2 %0, %1, %2, %0;" : "+l"(acc) : "l"(a), "l"(b));
}
__device__ __forceinline__ float2 unpack2(unsigned long long v) {
    float2 f;
    asm("mov.b64 {%0, %1}, %2;" : "=f"(f.x), "=f"(f.y) : "l"(v));
    return f;
}

// ---------------------------------------------------------------------------
// Kernel 0: detect int64 vs int32 token dtype.
// If tokens are int64 (LE), the odd 32-bit words of the first 32 elements are
// all zero (values < 32000). For real int32 data the probability of that is
// ~(1/32000)^32 ~ 0.
// ---------------------------------------------------------------------------
__global__ void detect_tok_kernel(const int* __restrict__ w) {
    int allz = 1;
    for (int i = 1; i < 64; i += 2)
        if (w[i] != 0) allz = 0;
    g_tok64 = allz;
}

// ---------------------------------------------------------------------------
// Kernel 1: x_proj = gather(emb, tok) @ W_ih^T + (b_ih + b_hh)
// Tiled fp32 GEMM, BM=BN=128, BK=16, 256 threads, 8x8 per thread,
// f32x2-packed FFMA (pairs along M; B operand pre-duplicated in smem).
// ---------------------------------------------------------------------------
__global__ void __launch_bounds__(256, 2)
xproj_kernel(const void* __restrict__ tok_raw,
             const float* __restrict__ emb,
             const float* __restrict__ W_ih,
             const float* __restrict__ b_ih,
             const float* __restrict__ b_hh)
{
    __shared__ float              As[16][128];      // A tile, [k][m]
    __shared__ unsigned long long Bsd[16][128];     // B tile, [k][n], value duplicated {v,v}
    __shared__ int                toks[128];

    const int tid = threadIdx.x;
    const int m0  = blockIdx.y * 128;
    const int n0  = blockIdx.x * 128;

    if (tid < 128) {
        int m = m0 + tid;
        toks[tid] = g_tok64 ? (int)((const long long*)tok_raw)[m]
                            : ((const int*)tok_raw)[m];
    }
    __syncthreads();

    const int ldr_m   = tid >> 1;        // 0..127
    const int ldr_seg = (tid & 1) * 8;   // 0 or 8
    const float* arow_base = emb  + (size_t)toks[ldr_m] * EMB + ldr_seg;
    const float* brow_base = W_ih + (size_t)(n0 + ldr_m) * EMB + ldr_seg;

    const int tx = tid & 15;   // n sub-tile
    const int ty = tid >> 4;   // m sub-tile

    unsigned long long acc[32]; // acc[i2*8+j] packs (m = ty*8+2*i2, m+1) x (n = n0+tx*8+j)
#pragma unroll
    for (int i = 0; i < 32; i++) acc[i] = 0ull;

    for (int kt = 0; kt < EMB / 16; kt++) {
        const int k0 = kt * 16;
        float4 av0 = *(const float4*)(arow_base + k0);
        float4 av1 = *(const float4*)(arow_base + k0 + 4);
        float4 bv0 = *(const float4*)(brow_base + k0);
        float4 bv1 = *(const float4*)(brow_base + k0 + 4);

        __syncthreads();   // previous tile fully consumed
        As[ldr_seg + 0][ldr_m] = av0.x;
        As[ldr_seg + 1][ldr_m] = av0.y;
        As[ldr_seg + 2][ldr_m] = av0.z;
        As[ldr_seg + 3][ldr_m] = av0.w;
        As[ldr_seg + 4][ldr_m] = av1.x;
        As[ldr_seg + 5][ldr_m] = av1.y;
        As[ldr_seg + 6][ldr_m] = av1.z;
        As[ldr_seg + 7][ldr_m] = av1.w;
        Bsd[ldr_seg + 0][ldr_m] = packdup(bv0.x);
        Bsd[ldr_seg + 1][ldr_m] = packdup(bv0.y);
        Bsd[ldr_seg + 2][ldr_m] = packdup(bv0.z);
        Bsd[ldr_seg + 3][ldr_m] = packdup(bv0.w);
        Bsd[ldr_seg + 4][ldr_m] = packdup(bv1.x);
        Bsd[ldr_seg + 5][ldr_m] = packdup(bv1.y);
        Bsd[ldr_seg + 6][ldr_m] = packdup(bv1.z);
        Bsd[ldr_seg + 7][ldr_m] = packdup(bv1.w);
        __syncthreads();

#pragma unroll
        for (int kk = 0; kk < 16; kk++) {
            ulonglong2 a01 = *(const ulonglong2*)&As[kk][ty * 8];
            ulonglong2 a23 = *(const ulonglong2*)&As[kk][ty * 8 + 4];
            unsigned long long ap[4] = { a01.x, a01.y, a23.x, a23.y };
            ulonglong2 b01 = *(const ulonglong2*)&Bsd[kk][tx * 8];
            ulonglong2 b23 = *(const ulonglong2*)&Bsd[kk][tx * 8 + 2];
            ulonglong2 b45 = *(const ulonglong2*)&Bsd[kk][tx * 8 + 4];
            ulonglong2 b67 = *(const ulonglong2*)&Bsd[kk][tx * 8 + 6];
            unsigned long long bd[8] = { b01.x, b01.y, b23.x, b23.y,
                                         b45.x, b45.y, b67.x, b67.y };
#pragma unroll
            for (int i2 = 0; i2 < 4; i2++)
#pragma unroll
                for (int j = 0; j < 8; j++)
                    ffma2(acc[i2 * 8 + j], ap[i2], bd[j]);
        }
    }

    // Epilogue: add (b_ih + b_hh), store to g_xproj
    float bias[8];
    {
        float4 x0 = *(const float4*)(b_ih + n0 + tx * 8);
        float4 x1 = *(const float4*)(b_ih + n0 + tx * 8 + 4);
        float4 y0 = *(const float4*)(b_hh + n0 + tx * 8);
        float4 y1 = *(const float4*)(b_hh + n0 + tx * 8 + 4);
        bias[0] = x0.x + y0.x;  bias[1] = x0.y + y0.y;
        bias[2] = x0.z + y0.z;  bias[3] = x0.w + y0.w;
        bias[4] = x1.x + y1.x;  bias[5] = x1.y + y1.y;
        bias[6] = x1.z + y1.z;  bias[7] = x1.w + y1.w;
    }
#pragma unroll
    for (int i2 = 0; i2 < 4; i2++) {
        float r0[8], r1[8];
#pragma unroll
        for (int j = 0; j < 8; j++) {
            float2 f = unpack2(acc[i2 * 8 + j]);
            r0[j] = f.x + bias[j];
            r1[j] = f.y + bias[j];
        }
        size_t mg = (size_t)(m0 + ty * 8 + i2 * 2);
        float* o0 = g_xproj + mg * HID + n0 + tx * 8;
        float* o1 = o0 + HID;
        *(float4*)(o0)     = make_float4(r0[0], r0[1], r0[2], r0[3]);
        *(float4*)(o0 + 4) = make_float4(r0[4], r0[5], r0[6], r0[7]);
        *(float4*)(o1)     = make_float4(r1[0], r1[1], r1[2], r1[3]);
        *(float4*)(o1 + 4) = make_float4(r1[4], r1[5], r1[6], r1[7]);
    }
}

// ---------------------------------------------------------------------------
// Kernel 2: recurrence.
// 16 clusters x 8 CTAs x 512 threads. Cluster g owns batches [4g, 4g+4).
// CTA rank j register-caches W_hh[:, 64j : 64j+64] (64 floats/thread, thread t
// owns output row h = t). Per step:
//   partials (f32x2 FFMA over local k-chunk) -> one st.shared::cluster.v4 per
//   thread to owner CTA -> barrier.cluster -> reduce 8 partials + xp, tanh,
//   write h-chunk (== next step's local k-input) + output row.
// W_hh never touches memory again after the initial load.
// ---------------------------------------------------------------------------
#define CSZ 8
#define BG  4
#define KC  64

__global__ void __cluster_dims__(CSZ, 1, 1) __launch_bounds__(512, 1)
rnn_kernel(const float* __restrict__ W_hh, float* __restrict__ out)
{
    __shared__ float h_own[BG][KC];             // this CTA's h-chunk, per batch
    __shared__ float recv[2][CSZ][BG * KC];     // [buf][src][hl*4 + b], 16 KB

    const int tid = threadIdx.x;
    unsigned int rank;
    asm("mov.u32 %0, %%cluster_ctarank;" : "=r"(rank));
    const int cluster_id = blockIdx.x / CSZ;
    const int batch_base = cluster_id * BG;

    // Register-resident W_hh chunk: thread t holds W_hh[t][rank*64 .. +63] as 32 packed pairs
    unsigned long long Wp[KC / 2];
    {
        const unsigned long long* wrow =
            (const unsigned long long*)(W_hh + (size_t)tid * HID + rank * KC);
#pragma unroll
        for (int i = 0; i < KC / 2; i++) Wp[i] = wrow[i];
    }

    if (tid < BG * KC) ((float*)h_own)[tid] = 0.0f;   // h0 = 0

    // Reduce-role (tid < 256): element (b = tid&3, hl = tid>>2) of own h-chunk
    const int rb  = tid & 3;
    const int rhl = tid >> 2;
    const float* xp_base  = g_xproj + (size_t)(batch_base + rb) * S_LEN * HID + rank * KC + rhl;
    float*       out_base = out     + (size_t)(batch_base + rb) * S_LEN * HID + rank * KC + rhl;

    // Writer-role: thread t's output row h = t belongs to CTA dst = t>>6
    const unsigned int dst = (unsigned)(tid >> 6);
    const int whl = tid & 63;
    const unsigned int recv_base_addr =
        (unsigned int)__cvta_generic_to_shared(&recv[0][rank][whl * 4]);
    // buf stride in bytes: CSZ*BG*KC*4 = 8192

    __syncthreads();
    asm volatile("barrier.cluster.arrive.aligned;" ::: "memory");
    asm volatile("barrier.cluster.wait.aligned;"   ::: "memory");

    int buf = 0;
    for (int s = 0; s < S_LEN; s++) {
        // Prefetch this step's xp early; consumed after the cluster barrier.
        float xpv = 0.0f;
        if (tid < 256) xpv = __ldg(xp_base + (size_t)s * HID);

        // Partial sums over local k-chunk for 4 batches (h = tid)
        float p[BG];
#pragma unroll
        for (int b = 0; b < BG; b++) {
            unsigned long long a0 = 0ull, a1 = 0ull;
            const ulonglong2* hb = (const ulonglong2*)h_own[b];
#pragma unroll
            for (int i = 0; i < KC / 4; i++) {
                ulonglong2 hv = hb[i];                 // 4 h values (broadcast LDS.128)
                ffma2(a0, Wp[2 * i],     hv.x);
                ffma2(a1, Wp[2 * i + 1], hv.y);
            }
            unsigned long long asum;
            asm("add.rn.f32x2 %0, %1, %2;" : "=l"(asum) : "l"(a0), "l"(a1));
            float2 f = unpack2(asum);
            p[b] = f.x + f.y;
        }

        // Ship partials (16 B) to the owner CTA's recv buffer
        {
            unsigned int laddr = recv_base_addr + (unsigned)buf * 8192u;
            unsigned int raddr;
            asm("mapa.shared::cluster.u32 %0, %1, %2;" : "=r"(raddr) : "r"(laddr), "r"(dst));
            asm volatile("st.shared::cluster.v4.b32 [%0], {%1, %2, %3, %4};"
                         :: "r"(raddr),
                            "r"(__float_as_uint(p[0])), "r"(__float_as_uint(p[1])),
                            "r"(__float_as_uint(p[2])), "r"(__float_as_uint(p[3]))
                         : "memory");
        }

        asm volatile("barrier.cluster.arrive.aligned;" ::: "memory");
        asm volatile("barrier.cluster.wait.aligned;"   ::: "memory");

        // Reduce + tanh + write-back (own h-chunk)
        if (tid < 256) {
            float sum = xpv;
#pragma unroll
            for (int src = 0; src < CSZ; src++)
                sum += recv[buf][src][tid];
            float val = tanhf(sum);
            h_own[rb][rhl] = val;
            out_base[(size_t)s * HID] = val;
        }
        __syncthreads();
        buf ^= 1;
    }

    // hidden = h_T, appended after outputs
    if (tid < 256) {
        out[(size_t)BATCH * S_LEN * HID +
            (size_t)(batch_base + rb) * HID + rank * KC + rhl] = h_own[rb][rhl];
    }
}

// ---------------------------------------------------------------------------
// Launch
// ---------------------------------------------------------------------------
extern "C" void kernel_launch(void* const* d_in, const int* in_sizes, int n_in,
                              void* d_out, int out_size)
{
    const void*  tok  = d_in[0];                 // (B,S) int32 or int64
    const float* emb  = (const float*)d_in[1];   // (V,E)
    const float* W_ih = (const float*)d_in[2];   // (H,E)
    const float* W_hh = (const float*)d_in[3];   // (H,H)
    const float* b_ih = (const float*)d_in[4];   // (H,)
    const float* b_hh = (const float*)d_in[5];   // (H,)
    float* out = (float*)d_out;                  // (B,S,H) outputs ++ (1,B,H) hidden

    detect_tok_kernel<<<1, 1>>>((const int*)tok);

    dim3 grid_p1(HID / 128, (BATCH * S_LEN) / 128);   // (4, 256)
    xproj_kernel<<<grid_p1, 256>>>(tok, emb, W_ih, b_ih, b_hh);

    rnn_kernel<<<(BATCH / BG) * CSZ, 512>>>(W_hh, out);  // 128 CTAs = 16 clusters of 8
}

// round 5
// speedup vs baseline: 1.2743x; 1.2743x over previous
#include <cuda_runtime.h>
#include <cstdint>
#include <cstddef>

// Problem dims
#define VOCAB 32000
#define EMB   512
#define HID   512
#define BATCH 64
#define S_LEN 512

// ---------------------------------------------------------------------------
// Scratch (no allocation allowed -> __device__ global)
// ---------------------------------------------------------------------------
__device__ float g_xproj[(size_t)BATCH * S_LEN * HID]; // 64 MB scratch

// ---------------------------------------------------------------------------
// Packed f32x2 helpers (Blackwell)
// ---------------------------------------------------------------------------
__device__ __forceinline__ unsigned long long packdup(float v) {
    unsigned long long r;
    asm("mov.b64 %0, {%1, %1};" : "=l"(r) : "f"(v));
    return r;
}
__device__ __forceinline__ unsigned long long pack2(float a, float b) {
    unsigned long long r;
    asm("mov.b64 %0, {%1, %2};" : "=l"(r) : "f"(a), "f"(b));
    return r;
}
__device__ __forceinline__ void ffma2(unsigned long long& acc,
                                      unsigned long long a,
                                      unsigned long long b) {
    asm("fma.rn.f32x2 %0, %1, %2, %0;" : "+l"(acc) : "l"(a), "l"(b));
}
__device__ __forceinline__ float2 unpack2(unsigned long long v) {
    float2 f;
    asm("mov.b64 {%0, %1}, %2;" : "=f"(f.x), "=f"(f.y) : "l"(v));
    return f;
}

// ---------------------------------------------------------------------------
// Kernel 1: x_proj = gather(emb, tok) @ W_ih^T + (b_ih + b_hh)
// BM=BN=128, BK=16, 256 threads, 8x8/thread, f32x2 FFMA.
// Thread map: ty = tid&15 (M sub-tile), tx = tid>>4 (N sub-tile) so that
// within a warp the B operand is a 2-address broadcast (conflict-free) and
// the staging STS is fully coalesced.
// Token dtype (int32 vs int64) detected per-block from the first 64 words.
// ---------------------------------------------------------------------------
__global__ void __launch_bounds__(256, 2)
xproj_kernel(const void* __restrict__ tok_raw,
             const float* __restrict__ emb,
             const float* __restrict__ W_ih,
             const float* __restrict__ b_ih,
             const float* __restrict__ b_hh)
{
    __shared__ float              As[16][128];      // A tile, [k][m]
    __shared__ unsigned long long Bsd[16][128];     // B tile, [k][n], dup {v,v}
    __shared__ int                toks[128];
    __shared__ int                s_tok64;

    const int tid = threadIdx.x;
    const int m0  = blockIdx.y * 128;
    const int n0  = blockIdx.x * 128;

    // int64 tokens (LE) => odd 32-bit words of the first 32 elements all zero.
    if (tid < 32) {
        int wv = ((const int*)tok_raw)[2 * tid + 1];
        unsigned nz = __ballot_sync(0xffffffffu, wv != 0);
        if (tid == 0) s_tok64 = (nz == 0u);
    }
    __syncthreads();

    if (tid < 128) {
        int m = m0 + tid;
        toks[tid] = s_tok64 ? (int)((const long long*)tok_raw)[m]
                            : ((const int*)tok_raw)[m];
    }
    __syncthreads();

    // Loaders: thread t loads row (t&127), k-seg ((t>>7)*8 .. +8)
    const int ldr_m   = tid & 127;
    const int ldr_seg = (tid >> 7) * 8;
    const float* arow_base = emb  + (size_t)toks[ldr_m] * EMB + ldr_seg;
    const float* brow_base = W_ih + (size_t)(n0 + ldr_m) * EMB + ldr_seg;

    const int ty = tid & 15;   // m sub-tile
    const int tx = tid >> 4;   // n sub-tile

    unsigned long long acc[32]; // acc[i2*8+j]: (m=ty*8+2*i2, m+1) x (n=n0+tx*8+j)
#pragma unroll
    for (int i = 0; i < 32; i++) acc[i] = 0ull;

    for (int kt = 0; kt < EMB / 16; kt++) {
        const int k0 = kt * 16;
        float4 av0 = *(const float4*)(arow_base + k0);
        float4 av1 = *(const float4*)(arow_base + k0 + 4);
        float4 bv0 = *(const float4*)(brow_base + k0);
        float4 bv1 = *(const float4*)(brow_base + k0 + 4);

        __syncthreads();   // previous tile fully consumed
        As[ldr_seg + 0][ldr_m] = av0.x;
        As[ldr_seg + 1][ldr_m] = av0.y;
        As[ldr_seg + 2][ldr_m] = av0.z;
        As[ldr_seg + 3][ldr_m] = av0.w;
        As[ldr_seg + 4][ldr_m] = av1.x;
        As[ldr_seg + 5][ldr_m] = av1.y;
        As[ldr_seg + 6][ldr_m] = av1.z;
        As[ldr_seg + 7][ldr_m] = av1.w;
        Bsd[ldr_seg + 0][ldr_m] = packdup(bv0.x);
        Bsd[ldr_seg + 1][ldr_m] = packdup(bv0.y);
        Bsd[ldr_seg + 2][ldr_m] = packdup(bv0.z);
        Bsd[ldr_seg + 3][ldr_m] = packdup(bv0.w);
        Bsd[ldr_seg + 4][ldr_m] = packdup(bv1.x);
        Bsd[ldr_seg + 5][ldr_m] = packdup(bv1.y);
        Bsd[ldr_seg + 6][ldr_m] = packdup(bv1.z);
        Bsd[ldr_seg + 7][ldr_m] = packdup(bv1.w);
        __syncthreads();

#pragma unroll
        for (int kk = 0; kk < 16; kk++) {
            ulonglong2 a01 = *(const ulonglong2*)&As[kk][ty * 8];
            ulonglong2 a23 = *(const ulonglong2*)&As[kk][ty * 8 + 4];
            unsigned long long ap[4] = { a01.x, a01.y, a23.x, a23.y };
            ulonglong2 b01 = *(const ulonglong2*)&Bsd[kk][tx * 8];
            ulonglong2 b23 = *(const ulonglong2*)&Bsd[kk][tx * 8 + 2];
            ulonglong2 b45 = *(const ulonglong2*)&Bsd[kk][tx * 8 + 4];
            ulonglong2 b67 = *(const ulonglong2*)&Bsd[kk][tx * 8 + 6];
            unsigned long long bd[8] = { b01.x, b01.y, b23.x, b23.y,
                                         b45.x, b45.y, b67.x, b67.y };
#pragma unroll
            for (int i2 = 0; i2 < 4; i2++)
#pragma unroll
                for (int j = 0; j < 8; j++)
                    ffma2(acc[i2 * 8 + j], ap[i2], bd[j]);
        }
    }

    // Epilogue: add (b_ih + b_hh), store
    float bias[8];
    {
        float4 x0 = *(const float4*)(b_ih + n0 + tx * 8);
        float4 x1 = *(const float4*)(b_ih + n0 + tx * 8 + 4);
        float4 y0 = *(const float4*)(b_hh + n0 + tx * 8);
        float4 y1 = *(const float4*)(b_hh + n0 + tx * 8 + 4);
        bias[0] = x0.x + y0.x;  bias[1] = x0.y + y0.y;
        bias[2] = x0.z + y0.z;  bias[3] = x0.w + y0.w;
        bias[4] = x1.x + y1.x;  bias[5] = x1.y + y1.y;
        bias[6] = x1.z + y1.z;  bias[7] = x1.w + y1.w;
    }
#pragma unroll
    for (int i2 = 0; i2 < 4; i2++) {
        float r0[8], r1[8];
#pragma unroll
        for (int j = 0; j < 8; j++) {
            float2 f = unpack2(acc[i2 * 8 + j]);
            r0[j] = f.x + bias[j];
            r1[j] = f.y + bias[j];
        }
        size_t mg = (size_t)(m0 + ty * 8 + i2 * 2);
        float* o0 = g_xproj + mg * HID + n0 + tx * 8;
        float* o1 = o0 + HID;
        *(float4*)(o0)     = make_float4(r0[0], r0[1], r0[2], r0[3]);
        *(float4*)(o0 + 4) = make_float4(r0[4], r0[5], r0[6], r0[7]);
        *(float4*)(o1)     = make_float4(r1[0], r1[1], r1[2], r1[3]);
        *(float4*)(o1 + 4) = make_float4(r1[4], r1[5], r1[6], r1[7]);
    }
}

// ---------------------------------------------------------------------------
// Kernel 2: recurrence, dataflow-synced via st.async + mbarrier (no per-step
// cluster barrier). 16 clusters x 8 CTAs x 512 threads; cluster g owns
// batches [4g,4g+4). CTA rank j register-caches W_hh[:, 64j:64j+64).
// Per step: partials (f32x2) -> st.async (16B/thread) to owner CTA with
// mbarrier complete_tx -> owner try_waits its own mbar (expects 8192B) ->
// reduce + tanh into double-buffered h_own -> one __syncthreads.
// Deadlock-freedom: a writer can issue step-(s+2) transactions to an owner's
// mbar only after the owner finished step s's phase AND re-armed expect_tx
// (see causality chain through the owner's end-of-step __syncthreads).
// ---------------------------------------------------------------------------
#define CSZ 8
#define BG  4
#define KC  64
#define STEP_TX (CSZ * KC * BG * 16 / 4)   /* 512 stores x 16B = 8192 */

__global__ void __cluster_dims__(CSZ, 1, 1) __launch_bounds__(512, 1)
rnn_kernel(const float* __restrict__ W_hh, float* __restrict__ out)
{
    __shared__ float h_own[2][BG][KC];          // double-buffered h chunk
    __shared__ float recv[2][CSZ][BG * KC];     // [buf][src][hl*4 + b]
    __shared__ unsigned long long mbar[2];

    const int tid = threadIdx.x;
    unsigned int rank;
    asm("mov.u32 %0, %%cluster_ctarank;" : "=r"(rank));
    const int cluster_id = blockIdx.x / CSZ;
    const int batch_base = cluster_id * BG;

    // Register-resident W_hh chunk: thread t holds W_hh[t][rank*64 .. +63]
    unsigned long long Wp[KC / 2];
    {
        const unsigned long long* wrow =
            (const unsigned long long*)(W_hh + (size_t)tid * HID + rank * KC);
#pragma unroll
        for (int i = 0; i < KC / 2; i++) Wp[i] = wrow[i];
    }

    if (tid < BG * KC) ((float*)h_own[0])[tid] = 0.0f;   // h0 = 0 (buffer 0)

    // mbarrier init + pre-post expects for the first two steps
    const unsigned int mbar0 = (unsigned int)__cvta_generic_to_shared(&mbar[0]);
    const unsigned int mbar1 = (unsigned int)__cvta_generic_to_shared(&mbar[1]);
    if (tid == 0) {
        asm volatile("mbarrier.init.shared.b64 [%0], 1;" :: "r"(mbar0) : "memory");
        asm volatile("mbarrier.init.shared.b64 [%0], 1;" :: "r"(mbar1) : "memory");
        asm volatile("mbarrier.arrive.expect_tx.shared.b64 _, [%0], %1;"
                     :: "r"(mbar0), "r"(STEP_TX) : "memory");
        asm volatile("mbarrier.arrive.expect_tx.shared.b64 _, [%0], %1;"
                     :: "r"(mbar1), "r"(STEP_TX) : "memory");
    }

    // Reduce-role (tid < 256): element (b = tid&3, hl = tid>>2)
    const int rb  = tid & 3;
    const int rhl = tid >> 2;
    const float* xp_base  = g_xproj + (size_t)(batch_base + rb) * S_LEN * HID + rank * KC + rhl;
    float*       out_base = out     + (size_t)(batch_base + rb) * S_LEN * HID + rank * KC + rhl;

    // Writer-role: thread t's output row h = t lives in CTA dst = t>>6
    const unsigned int dst = (unsigned)(tid >> 6);
    const int whl = tid & 63;
    unsigned int rdata[2], rmbar[2];
#pragma unroll
    for (int b = 0; b < 2; b++) {
        unsigned int laddr =
            (unsigned int)__cvta_generic_to_shared(&recv[b][rank][whl * 4]);
        asm("mapa.shared::cluster.u32 %0, %1, %2;" : "=r"(rdata[b]) : "r"(laddr), "r"(dst));
        unsigned int lm = b ? mbar1 : mbar0;
        asm("mapa.shared::cluster.u32 %0, %1, %2;" : "=r"(rmbar[b]) : "r"(lm), "r"(dst));
    }

    __syncthreads();
    asm volatile("barrier.cluster.arrive.aligned;" ::: "memory");
    asm volatile("barrier.cluster.wait.aligned;"   ::: "memory");

    for (int s = 0; s < S_LEN; s++) {
        const int buf = s & 1;
        const int cur = s & 1;          // h buffer read this step
        const int nxt = cur ^ 1;        // h buffer written this step

        // Prefetch this step's xp (consumed after the mbar wait)
        float xpv = 0.0f;
        if (tid < 256) xpv = __ldg(xp_base + (size_t)s * HID);

        // Partials over local k-chunk, 4 batches; ship pairs as computed
        float p[BG];
#pragma unroll
        for (int b = 0; b < BG; b++) {
            unsigned long long a0 = 0ull, a1 = 0ull;
            const ulonglong2* hb = (const ulonglong2*)h_own[cur][b];
#pragma unroll
            for (int i = 0; i < KC / 4; i++) {
                ulonglong2 hv = hb[i];
                ffma2(a0, Wp[2 * i],     hv.x);
                ffma2(a1, Wp[2 * i + 1], hv.y);
            }
            unsigned long long asum;
            asm("add.rn.f32x2 %0, %1, %2;" : "=l"(asum) : "l"(a0), "l"(a1));
            float2 f = unpack2(asum);
            p[b] = f.x + f.y;
            if (b == 1) {
                asm volatile("st.async.shared::cluster.mbarrier::complete_tx::bytes.b64 [%0], %1, [%2];"
                             :: "r"(rdata[buf]), "l"(pack2(p[0], p[1])), "r"(rmbar[buf]) : "memory");
            }
        }
        asm volatile("st.async.shared::cluster.mbarrier::complete_tx::bytes.b64 [%0], %1, [%2];"
                     :: "r"(rdata[buf] + 8), "l"(pack2(p[2], p[3])), "r"(rmbar[buf]) : "memory");

        // Owner side: wait for all 8192 bytes of this step's partials
        if (tid < 256) {
            const unsigned int mb = buf ? mbar1 : mbar0;
            const unsigned int parity = (unsigned)(s >> 1) & 1u;
            unsigned int done;
            asm volatile(
                "{\n\t.reg .pred p;\n\t"
                "mbarrier.try_wait.parity.acquire.cluster.shared::cta.b64 p, [%1], %2;\n\t"
                "selp.b32 %0, 1, 0, p;\n\t}"
                : "=r"(done) : "r"(mb), "r"(parity) : "memory");
            if (!done) {
                asm volatile(
                    "{\n\t.reg .pred P1;\n\t"
                    "WL_%=:\n\t"
                    "mbarrier.try_wait.parity.acquire.cluster.shared::cta.b64 P1, [%0], %1, 0x989680;\n\t"
                    "@P1 bra.uni WD_%=;\n\t"
                    "bra.uni WL_%=;\n\t"
                    "WD_%=:\n\t}"
                    :: "r"(mb), "r"(parity) : "memory");
            }

            // Reduce 8 partials + xp, tanh, write next h buffer + output
            float sum = xpv;
#pragma unroll
            for (int src = 0; src < CSZ; src++)
                sum += recv[buf][src][tid];
            float val = tanhf(sum);
            h_own[nxt][rb][rhl] = val;
            out_base[(size_t)s * HID] = val;

            // Re-arm this mbar for its next usage (step s+2)
            if (tid == 0) {
                asm volatile("mbarrier.arrive.expect_tx.shared.b64 _, [%0], %1;"
                             :: "r"(mb), "r"(STEP_TX) : "memory");
            }
        }
        __syncthreads();   // h_own[nxt] visible to all before next step
    }

    // hidden = h_T (final state lives in buffer S_LEN&1 = 0)
    if (tid < 256) {
        out[(size_t)BATCH * S_LEN * HID +
            (size_t)(batch_base + rb) * HID + rank * KC + rhl] = h_own[S_LEN & 1][rb][rhl];
    }

    asm volatile("barrier.cluster.arrive.aligned;" ::: "memory");
    asm volatile("barrier.cluster.wait.aligned;"   ::: "memory");
}

// ---------------------------------------------------------------------------
// Launch
// ---------------------------------------------------------------------------
extern "C" void kernel_launch(void* const* d_in, const int* in_sizes, int n_in,
                              void* d_out, int out_size)
{
    const void*  tok  = d_in[0];                 // (B,S) int32 or int64
    const float* emb  = (const float*)d_in[1];   // (V,E)
    const float* W_ih = (const float*)d_in[2];   // (H,E)
    const float* W_hh = (const float*)d_in[3];   // (H,H)
    const float* b_ih = (const float*)d_in[4];   // (H,)
    const float* b_hh = (const float*)d_in[5];   // (H,)
    float* out = (float*)d_out;                  // (B,S,H) outputs ++ (1,B,H) hidden

    dim3 grid_p1(HID / 128, (BATCH * S_LEN) / 128);   // (4, 256)
    xproj_kernel<<<grid_p1, 256>>>(tok, emb, W_ih, b_ih, b_hh);

    rnn_kernel<<<(BATCH / BG) * CSZ, 512>>>(W_hh, out);  // 128 CTAs = 16 clusters
}